// round 2
// baseline (speedup 1.0000x reference)
#include <cuda_runtime.h>
#include <math.h>

#define NN 20000
#define FF 8
#define PP 12
#define OO 32
#define EE 320000
#define FP (FF*PP)   // 96 floats per node

// ---- scratch (static device globals; no allocation allowed) ----
__device__ int   g_cnt[NN];        // in-degree histogram
__device__ int   g_rowoff[NN + 1]; // CSR row offsets (by dst)
__device__ int   g_cursor[NN];     // scatter cursors
__device__ int   g_col[EE];        // CSR column (src) indices
__device__ float g_dinv[NN];       // (in_deg + 1)^-1/2
__device__ float g_cwz[FF * OO];   // fused  Wz @ Lz^T   [F][O]
__device__ float g_cwh[FF * OO];   // fused  Wh @ Lh^T   [F][O]
__device__ float g_cbz[OO];        // fused  bz @ Lz^T + lz_b
__device__ float g_cbh[OO];
__device__ float g_probs[PP];      // softmax(att)

// ---------------------------------------------------------------------------
// K0: zero the histogram (all blocks, grid-stride) + fold GCN weights into the
//     GRU linears and softmax(att) (block 0 only; exact because H == 0).
// ---------------------------------------------------------------------------
__global__ void prep_kernel(const float* __restrict__ Wz, const float* __restrict__ bz,
                            const float* __restrict__ Wh, const float* __restrict__ bh,
                            const float* __restrict__ lzw, const float* __restrict__ lzb,
                            const float* __restrict__ lhw, const float* __restrict__ lhb,
                            const float* __restrict__ att) {
    int gid = blockIdx.x * blockDim.x + threadIdx.x;
    int stride = gridDim.x * blockDim.x;
    for (int j = gid; j < NN; j += stride) g_cnt[j] = 0;

    if (blockIdx.x != 0) return;
    int t = threadIdx.x;
    if (t < 256) {                       // W'_z[f][o] = sum_k Wz[f][k] * lzw[o][k]
        int f = t >> 5, o = t & 31;
        float s = 0.f;
        #pragma unroll
        for (int k = 0; k < 32; ++k) s = fmaf(Wz[f * 32 + k], lzw[o * 64 + k], s);
        g_cwz[t] = s;
    } else {                             // W'_h
        int i = t - 256;
        int f = i >> 5, o = i & 31;
        float s = 0.f;
        #pragma unroll
        for (int k = 0; k < 32; ++k) s = fmaf(Wh[f * 32 + k], lhw[o * 64 + k], s);
        g_cwh[i] = s;
    }
    if (t < 32) {                        // b'_z[o] = lz_b[o] + sum_k bz[k]*lzw[o][k]
        float s = lzb[t];
        #pragma unroll
        for (int k = 0; k < 32; ++k) s = fmaf(bz[k], lzw[t * 64 + k], s);
        g_cbz[t] = s;
    } else if (t < 64) {
        int o = t - 32;
        float s = lhb[o];
        #pragma unroll
        for (int k = 0; k < 32; ++k) s = fmaf(bh[k], lhw[o * 64 + k], s);
        g_cbh[o] = s;
    }
    if (t == 0) {                        // softmax over 12 logits
        float m = att[0];
        for (int p = 1; p < PP; ++p) m = fmaxf(m, att[p]);
        float e[PP], sum = 0.f;
        for (int p = 0; p < PP; ++p) { e[p] = __expf(att[p] - m); sum += e[p]; }
        float inv = 1.f / sum;
        for (int p = 0; p < PP; ++p) g_probs[p] = e[p] * inv;
    }
}

// K1: in-degree histogram over dst
__global__ void deg_kernel(const int* __restrict__ ei) {
    int e = blockIdx.x * blockDim.x + threadIdx.x;
    if (e < EE) atomicAdd(&g_cnt[ei[EE + e]], 1);
}

// ---------------------------------------------------------------------------
// K2: single-block exclusive scan of g_cnt -> rowoff/cursor, plus dinv.
//     1024 threads x 20 items = 20480 >= NN.
// ---------------------------------------------------------------------------
__global__ void scan_kernel() {
    const int IT = 20;
    __shared__ int part[1024];
    int t = threadIdx.x;
    int base = t * IT;
    int local[IT];
    int sum = 0;
    #pragma unroll
    for (int i = 0; i < IT; ++i) {
        int idx = base + i;
        int c = (idx < NN) ? g_cnt[idx] : 0;
        local[i] = sum;          // thread-local exclusive prefix
        sum += c;
    }
    part[t] = sum;
    __syncthreads();
    // Hillis-Steele inclusive scan over the 1024 partials
    for (int off = 1; off < 1024; off <<= 1) {
        int v = (t >= off) ? part[t - off] : 0;
        __syncthreads();
        part[t] += v;
        __syncthreads();
    }
    int prefix = (t == 0) ? 0 : part[t - 1];
    #pragma unroll
    for (int i = 0; i < IT; ++i) {
        int idx = base + i;
        if (idx < NN) {
            int st = prefix + local[i];
            g_rowoff[idx] = st;
            g_cursor[idx] = st;
            g_dinv[idx]   = rsqrtf((float)(g_cnt[idx] + 1));  // +1 = self loop
        }
    }
    if (t == 0) g_rowoff[NN] = EE;
}

// K3: scatter src indices into dst-sorted CSR
__global__ void scatter_kernel(const int* __restrict__ ei) {
    int e = blockIdx.x * blockDim.x + threadIdx.x;
    if (e >= EE) return;
    int s = ei[e];
    int d = ei[EE + e];
    int pos = atomicAdd(&g_cursor[d], 1);
    g_col[pos] = s;
}

// ---------------------------------------------------------------------------
// K4: fused gather + GRU + temporal attention + readout.
//     One warp per node. Gather phase: lane covers features {lane, lane+32,
//     lane+64} (coalesced 128B lines per src row). GRU phase: lane = channel o.
// ---------------------------------------------------------------------------
__global__ void __launch_bounds__(256) node_kernel(
        const float* __restrict__ x,
        const float* __restrict__ out_w,
        const float* __restrict__ out_b,
        float* __restrict__ out) {
    __shared__ float buf[8][FP];
    int warp = threadIdx.x >> 5;
    int lane = threadIdx.x & 31;
    int node = blockIdx.x * 8 + warp;
    if (node >= NN) return;

    int beg = __ldg(&g_rowoff[node]);
    int end = __ldg(&g_rowoff[node + 1]);
    float di = g_dinv[node];

    // acc = sum_e dinv[src] * x[src]  (di factored out)
    float a0 = 0.f, a1 = 0.f, a2 = 0.f;
    int j = beg;
    for (; j + 1 < end; j += 2) {
        int s0 = __ldg(&g_col[j]);
        int s1 = __ldg(&g_col[j + 1]);
        float w0 = __ldg(&g_dinv[s0]);
        float w1 = __ldg(&g_dinv[s1]);
        const float* x0 = x + (size_t)s0 * FP;
        const float* x1 = x + (size_t)s1 * FP;
        float v00 = __ldg(x0 + lane), v01 = __ldg(x0 + lane + 32), v02 = __ldg(x0 + lane + 64);
        float v10 = __ldg(x1 + lane), v11 = __ldg(x1 + lane + 32), v12 = __ldg(x1 + lane + 64);
        a0 = fmaf(w0, v00, a0); a1 = fmaf(w0, v01, a1); a2 = fmaf(w0, v02, a2);
        a0 = fmaf(w1, v10, a0); a1 = fmaf(w1, v11, a1); a2 = fmaf(w1, v12, a2);
    }
    if (j < end) {
        int s0 = __ldg(&g_col[j]);
        float w0 = __ldg(&g_dinv[s0]);
        const float* x0 = x + (size_t)s0 * FP;
        a0 = fmaf(w0, __ldg(x0 + lane),      a0);
        a1 = fmaf(w0, __ldg(x0 + lane + 32), a1);
        a2 = fmaf(w0, __ldg(x0 + lane + 64), a2);
    }
    // agg = di * (acc + di * x_self)
    const float* xs = x + (size_t)node * FP;
    a0 = di * fmaf(di, __ldg(xs + lane),      a0);
    a1 = di * fmaf(di, __ldg(xs + lane + 32), a1);
    a2 = di * fmaf(di, __ldg(xs + lane + 64), a2);

    buf[warp][lane]      = a0;
    buf[warp][lane + 32] = a1;
    buf[warp][lane + 64] = a2;
    __syncwarp();

    float wz[FF], wh[FF];
    #pragma unroll
    for (int f = 0; f < FF; ++f) {
        wz[f] = g_cwz[f * OO + lane];
        wh[f] = g_cwh[f * OO + lane];
    }
    float bz_ = g_cbz[lane];
    float bh_ = g_cbh[lane];

    float hacc = 0.f;
    #pragma unroll
    for (int p = 0; p < PP; ++p) {
        float z = bz_, h = bh_;
        #pragma unroll
        for (int f = 0; f < FF; ++f) {
            float v = buf[warp][f * PP + p];   // broadcast LDS
            z = fmaf(v, wz[f], z);
            h = fmaf(v, wh[f], h);
        }
        float Z = 1.f / (1.f + __expf(-z));                 // sigmoid
        float T = 2.f / (1.f + __expf(-2.f * h)) - 1.f;     // tanh
        hacc = fmaf(g_probs[p], (1.f - Z) * T, hacc);       // (1-Z)*Ht weighted (H==0)
    }
    float hr = fmaxf(hacc, 0.f);   // relu

    // out[node][p] = sum_o hr[o] * out_w[p][o] + out_b[p]
    #pragma unroll
    for (int p = 0; p < PP; ++p) {
        float v = hr * __ldg(&out_w[p * OO + lane]);
        v += __shfl_xor_sync(0xffffffffu, v, 16);
        v += __shfl_xor_sync(0xffffffffu, v, 8);
        v += __shfl_xor_sync(0xffffffffu, v, 4);
        v += __shfl_xor_sync(0xffffffffu, v, 2);
        v += __shfl_xor_sync(0xffffffffu, v, 1);
        if (lane == 0) out[node * PP + p] = v + __ldg(&out_b[p]);
    }
}

// ---------------------------------------------------------------------------
extern "C" void kernel_launch(void* const* d_in, const int* in_sizes, int n_in,
                              void* d_out, int out_size) {
    const float* x    = (const float*)d_in[0];
    const int*   ei   = (const int*)  d_in[1];
    const float* Wz   = (const float*)d_in[2];
    const float* bz   = (const float*)d_in[3];
    // d_in[4], d_in[5]: Wr, br  — unused (reset gate is dead code: H == 0)
    const float* Wh   = (const float*)d_in[6];
    const float* bh   = (const float*)d_in[7];
    const float* lzw  = (const float*)d_in[8];
    const float* lzb  = (const float*)d_in[9];
    // d_in[10], d_in[11]: lr_w, lr_b — unused
    const float* lhw  = (const float*)d_in[12];
    const float* lhb  = (const float*)d_in[13];
    const float* att  = (const float*)d_in[14];
    const float* outw = (const float*)d_in[15];
    const float* outb = (const float*)d_in[16];
    float* out = (float*)d_out;

    prep_kernel<<<40, 512>>>(Wz, bz, Wh, bh, lzw, lzb, lhw, lhb, att);
    deg_kernel<<<(EE + 255) / 256, 256>>>(ei);
    scan_kernel<<<1, 1024>>>();
    scatter_kernel<<<(EE + 255) / 256, 256>>>(ei);
    node_kernel<<<(NN + 7) / 8, 256>>>(x, outw, outb, out);
}

// round 3
// speedup vs baseline: 1.2445x; 1.2445x over previous
#include <cuda_runtime.h>
#include <math.h>

#define NN 20000
#define FF 8
#define PP 12
#define OO 32
#define EE 320000
#define FP (FF*PP)   // 96 floats per node

// ---- scratch (static device globals; no allocation allowed) ----
__device__ int   g_cnt[NN];        // in-degree histogram
__device__ int   g_rowoff[NN + 1]; // CSR row offsets (by dst)
__device__ int   g_cursor[NN];     // scatter cursors
__device__ int   g_col[EE];        // CSR column (src) indices
__device__ float g_dinv[NN];       // (in_deg + 1)^-1/2
__device__ float g_cwz[FF * OO];   // fused  Wz @ Lz^T   [F][O]
__device__ float g_cwh[FF * OO];   // fused  Wh @ Lh^T   [F][O]
__device__ float g_cbz[OO];        // fused  bz @ Lz^T + lz_b
__device__ float g_cbh[OO];
__device__ float g_probs[PP];      // softmax(att)

// ---------------------------------------------------------------------------
// K0: zero the histogram (grid-stride) + fold GCN weights into the GRU
//     linears and softmax(att) (block 0; exact because H == 0).
// ---------------------------------------------------------------------------
__global__ void prep_kernel(const float* __restrict__ Wz, const float* __restrict__ bz,
                            const float* __restrict__ Wh, const float* __restrict__ bh,
                            const float* __restrict__ lzw, const float* __restrict__ lzb,
                            const float* __restrict__ lhw, const float* __restrict__ lhb,
                            const float* __restrict__ att) {
    int gid = blockIdx.x * blockDim.x + threadIdx.x;
    int stride = gridDim.x * blockDim.x;
    for (int j = gid; j < NN; j += stride) g_cnt[j] = 0;

    if (blockIdx.x != 0) return;
    int t = threadIdx.x;
    if (t < 256) {                       // W'_z[f][o] = sum_k Wz[f][k] * lzw[o][k]
        int f = t >> 5, o = t & 31;
        float s = 0.f;
        #pragma unroll
        for (int k = 0; k < 32; ++k) s = fmaf(Wz[f * 32 + k], lzw[o * 64 + k], s);
        g_cwz[t] = s;
    } else {                             // W'_h
        int i = t - 256;
        int f = i >> 5, o = i & 31;
        float s = 0.f;
        #pragma unroll
        for (int k = 0; k < 32; ++k) s = fmaf(Wh[f * 32 + k], lhw[o * 64 + k], s);
        g_cwh[i] = s;
    }
    if (t < 32) {                        // b'_z[o] = lz_b[o] + sum_k bz[k]*lzw[o][k]
        float s = lzb[t];
        #pragma unroll
        for (int k = 0; k < 32; ++k) s = fmaf(bz[k], lzw[t * 64 + k], s);
        g_cbz[t] = s;
    } else if (t < 64) {
        int o = t - 32;
        float s = lhb[o];
        #pragma unroll
        for (int k = 0; k < 32; ++k) s = fmaf(bh[k], lhw[o * 64 + k], s);
        g_cbh[o] = s;
    }
    if (t == 0) {                        // softmax over 12 logits
        float m = att[0];
        for (int p = 1; p < PP; ++p) m = fmaxf(m, att[p]);
        float e[PP], sum = 0.f;
        for (int p = 0; p < PP; ++p) { e[p] = __expf(att[p] - m); sum += e[p]; }
        float inv = 1.f / sum;
        for (int p = 0; p < PP; ++p) g_probs[p] = e[p] * inv;
    }
}

// ---------------------------------------------------------------------------
// K1: in-degree histogram over dst. 4 edges per thread (int4 load) for MLP.
// ---------------------------------------------------------------------------
__global__ void deg_kernel(const int* __restrict__ ei) {
    int q = blockIdx.x * blockDim.x + threadIdx.x;   // quad index
    if (q >= EE / 4) return;
    int4 d4 = ((const int4*)(ei + EE))[q];
    atomicAdd(&g_cnt[d4.x], 1);
    atomicAdd(&g_cnt[d4.y], 1);
    atomicAdd(&g_cnt[d4.z], 1);
    atomicAdd(&g_cnt[d4.w], 1);
}

// ---------------------------------------------------------------------------
// K2: single-block tiled scan (coalesced). 1024 threads, 20 tiles of 1024.
//     Produces rowoff (exclusive prefix), cursor copy, and dinv.
// ---------------------------------------------------------------------------
__global__ void scan_kernel() {
    __shared__ int wsum[32];
    int t = threadIdx.x;
    int lane = t & 31, warp = t >> 5;
    int running = 0;                      // uniform across threads

    for (int tile = 0; tile < 20; ++tile) {
        int idx = tile * 1024 + t;
        int v = (idx < NN) ? g_cnt[idx] : 0;   // coalesced

        // inclusive warp scan
        int inc = v;
        #pragma unroll
        for (int off = 1; off < 32; off <<= 1) {
            int u = __shfl_up_sync(0xffffffffu, inc, off);
            if (lane >= off) inc += u;
        }
        if (lane == 31) wsum[warp] = inc;
        __syncthreads();
        if (warp == 0) {
            int w = wsum[lane];
            int wi = w;
            #pragma unroll
            for (int off = 1; off < 32; off <<= 1) {
                int u = __shfl_up_sync(0xffffffffu, wi, off);
                if (lane >= off) wi += u;
            }
            wsum[lane] = wi - w;          // exclusive warp offsets
        }
        __syncthreads();
        int excl = running + wsum[warp] + inc - v;

        if (idx < NN) {
            g_rowoff[idx] = excl;
            g_cursor[idx] = excl;
            g_dinv[idx]   = rsqrtf((float)(v + 1));   // +1 = self loop
        }
        // tile total = last warp's inclusive total; broadcast via smem
        __syncthreads();
        if (t == 1023) wsum[0] = running + wsum[31] + inc; // unused slot trick
        __syncthreads();
        running = wsum[0];
        __syncthreads();
    }
    if (t == 0) g_rowoff[NN] = EE;
}

// ---------------------------------------------------------------------------
// K3: scatter src indices into dst-sorted CSR. 4 edges/thread for MLP.
// ---------------------------------------------------------------------------
__global__ void scatter_kernel(const int* __restrict__ ei) {
    int q = blockIdx.x * blockDim.x + threadIdx.x;
    if (q >= EE / 4) return;
    int4 s4 = ((const int4*)ei)[q];
    int4 d4 = ((const int4*)(ei + EE))[q];
    int p0 = atomicAdd(&g_cursor[d4.x], 1);
    int p1 = atomicAdd(&g_cursor[d4.y], 1);
    int p2 = atomicAdd(&g_cursor[d4.z], 1);
    int p3 = atomicAdd(&g_cursor[d4.w], 1);
    g_col[p0] = s4.x;
    g_col[p1] = s4.y;
    g_col[p2] = s4.z;
    g_col[p3] = s4.w;
}

// ---------------------------------------------------------------------------
// K4: fused gather + GRU + temporal attention + readout.
//     One warp per node. Gather: unroll-4, all loads batched for MLP>=12.
// ---------------------------------------------------------------------------
__global__ void __launch_bounds__(256) node_kernel(
        const float* __restrict__ x,
        const float* __restrict__ out_w,
        const float* __restrict__ out_b,
        float* __restrict__ out) {
    __shared__ float buf[8][FP];
    int warp = threadIdx.x >> 5;
    int lane = threadIdx.x & 31;
    int node = blockIdx.x * 8 + warp;
    if (node >= NN) return;

    int beg = g_rowoff[node];
    int end = g_rowoff[node + 1];
    float di = g_dinv[node];

    float a0 = 0.f, a1 = 0.f, a2 = 0.f;
    int j = beg;
    for (; j + 4 <= end; j += 4) {
        int s0 = g_col[j], s1 = g_col[j+1], s2 = g_col[j+2], s3 = g_col[j+3];
        float w0 = g_dinv[s0], w1 = g_dinv[s1], w2 = g_dinv[s2], w3 = g_dinv[s3];
        const float* x0 = x + (size_t)s0 * FP;
        const float* x1 = x + (size_t)s1 * FP;
        const float* x2 = x + (size_t)s2 * FP;
        const float* x3 = x + (size_t)s3 * FP;
        float v00 = x0[lane], v01 = x0[lane+32], v02 = x0[lane+64];
        float v10 = x1[lane], v11 = x1[lane+32], v12 = x1[lane+64];
        float v20 = x2[lane], v21 = x2[lane+32], v22 = x2[lane+64];
        float v30 = x3[lane], v31 = x3[lane+32], v32 = x3[lane+64];
        a0 = fmaf(w0, v00, a0); a1 = fmaf(w0, v01, a1); a2 = fmaf(w0, v02, a2);
        a0 = fmaf(w1, v10, a0); a1 = fmaf(w1, v11, a1); a2 = fmaf(w1, v12, a2);
        a0 = fmaf(w2, v20, a0); a1 = fmaf(w2, v21, a1); a2 = fmaf(w2, v22, a2);
        a0 = fmaf(w3, v30, a0); a1 = fmaf(w3, v31, a1); a2 = fmaf(w3, v32, a2);
    }
    for (; j < end; ++j) {
        int s0 = g_col[j];
        float w0 = g_dinv[s0];
        const float* x0 = x + (size_t)s0 * FP;
        a0 = fmaf(w0, x0[lane],      a0);
        a1 = fmaf(w0, x0[lane + 32], a1);
        a2 = fmaf(w0, x0[lane + 64], a2);
    }
    // agg = di * (acc + di * x_self)
    const float* xs = x + (size_t)node * FP;
    a0 = di * fmaf(di, xs[lane],      a0);
    a1 = di * fmaf(di, xs[lane + 32], a1);
    a2 = di * fmaf(di, xs[lane + 64], a2);

    buf[warp][lane]      = a0;
    buf[warp][lane + 32] = a1;
    buf[warp][lane + 64] = a2;
    __syncwarp();

    float wz[FF], wh[FF];
    #pragma unroll
    for (int f = 0; f < FF; ++f) {
        wz[f] = g_cwz[f * OO + lane];
        wh[f] = g_cwh[f * OO + lane];
    }
    float bz_ = g_cbz[lane];
    float bh_ = g_cbh[lane];

    float hacc = 0.f;
    #pragma unroll
    for (int p = 0; p < PP; ++p) {
        float z = bz_, h = bh_;
        #pragma unroll
        for (int f = 0; f < FF; ++f) {
            float v = buf[warp][f * PP + p];   // broadcast LDS
            z = fmaf(v, wz[f], z);
            h = fmaf(v, wh[f], h);
        }
        float Z = 1.f / (1.f + __expf(-z));                 // sigmoid
        float T = 2.f / (1.f + __expf(-2.f * h)) - 1.f;     // tanh
        hacc = fmaf(g_probs[p], (1.f - Z) * T, hacc);       // (1-Z)*Ht (H==0)
    }
    float hr = fmaxf(hacc, 0.f);   // relu

    #pragma unroll
    for (int p = 0; p < PP; ++p) {
        float v = hr * __ldg(&out_w[p * OO + lane]);
        v += __shfl_xor_sync(0xffffffffu, v, 16);
        v += __shfl_xor_sync(0xffffffffu, v, 8);
        v += __shfl_xor_sync(0xffffffffu, v, 4);
        v += __shfl_xor_sync(0xffffffffu, v, 2);
        v += __shfl_xor_sync(0xffffffffu, v, 1);
        if (lane == 0) out[node * PP + p] = v + __ldg(&out_b[p]);
    }
}

// ---------------------------------------------------------------------------
extern "C" void kernel_launch(void* const* d_in, const int* in_sizes, int n_in,
                              void* d_out, int out_size) {
    const float* x    = (const float*)d_in[0];
    const int*   ei   = (const int*)  d_in[1];
    const float* Wz   = (const float*)d_in[2];
    const float* bz   = (const float*)d_in[3];
    // d_in[4], d_in[5]: Wr, br  — unused (reset gate dead: H == 0)
    const float* Wh   = (const float*)d_in[6];
    const float* bh   = (const float*)d_in[7];
    const float* lzw  = (const float*)d_in[8];
    const float* lzb  = (const float*)d_in[9];
    // d_in[10], d_in[11]: lr_w, lr_b — unused
    const float* lhw  = (const float*)d_in[12];
    const float* lhb  = (const float*)d_in[13];
    const float* att  = (const float*)d_in[14];
    const float* outw = (const float*)d_in[15];
    const float* outb = (const float*)d_in[16];
    float* out = (float*)d_out;

    prep_kernel<<<40, 512>>>(Wz, bz, Wh, bh, lzw, lzb, lhw, lhb, att);
    deg_kernel<<<(EE / 4 + 255) / 256, 256>>>(ei);
    scan_kernel<<<1, 1024>>>();
    scatter_kernel<<<(EE / 4 + 255) / 256, 256>>>(ei);
    node_kernel<<<(NN + 7) / 8, 256>>>(x, outw, outb, out);
}